// round 1
// baseline (speedup 1.0000x reference)
#include <cuda_runtime.h>
#include <math_constants.h>

// SubsetOperator: soft k-hot relaxation.
// Reference per-row math (TAU=1):
//   s = scores + g
//   repeat K=16: s += log(max(1-onehot, EPS)); onehot = softmax(s); khot += onehot
// Equivalent tracked in exp-domain with e = exp(s - rowmax):
//   repeat K=16: Z = sum(e); p = e/Z; khot += p; e *= max(1-p, EPS)
// (softmax(s + log m) == e*m / sum(e*m)) -> no per-iteration exp/log needed.

#define ROWS 4096
#define NCOL 8192
#define THREADS 1024
#define EPT 8              // elements per thread (NCOL / THREADS)
#define KITER 16
#define EPSF 1.1754943508222875e-38f   // float32 tiny

__device__ __forceinline__ float warpRedSum(float v) {
#pragma unroll
    for (int o = 16; o > 0; o >>= 1) v += __shfl_xor_sync(0xffffffffu, v, o);
    return v;
}

__device__ __forceinline__ float warpRedMax(float v) {
#pragma unroll
    for (int o = 16; o > 0; o >>= 1) v = fmaxf(v, __shfl_xor_sync(0xffffffffu, v, o));
    return v;
}

__global__ void __launch_bounds__(THREADS, 1)
subset_op_kernel(const float* __restrict__ scores,
                 const float* __restrict__ g,
                 float* __restrict__ out) {
    __shared__ float red[32];
    __shared__ float bcast;

    const int row  = blockIdx.x;
    const int tid  = threadIdx.x;
    const int lane = tid & 31;
    const int wid  = tid >> 5;

    const float4* __restrict__ s4 = (const float4*)(scores + (size_t)row * NCOL);
    const float4* __restrict__ g4 = (const float4*)(g      + (size_t)row * NCOL);
    float4* __restrict__ o4       = (float4*)(out          + (size_t)row * NCOL);

    float sv[EPT];
    float m = -CUDART_INF_F;

    // Coalesced load: 2 float4 per thread, stride THREADS in float4 units.
#pragma unroll
    for (int c = 0; c < EPT / 4; c++) {
        float4 a = s4[tid + c * THREADS];
        float4 b = g4[tid + c * THREADS];
        sv[c * 4 + 0] = a.x + b.x;
        sv[c * 4 + 1] = a.y + b.y;
        sv[c * 4 + 2] = a.z + b.z;
        sv[c * 4 + 3] = a.w + b.w;
#pragma unroll
        for (int j = 0; j < 4; j++) m = fmaxf(m, sv[c * 4 + j]);
    }

    // Block max
    m = warpRedMax(m);
    if (lane == 0) red[wid] = m;
    __syncthreads();
    if (wid == 0) {
        float t = red[lane];
        t = warpRedMax(t);
        if (lane == 0) bcast = t;
    }
    __syncthreads();
    m = bcast;

    // e = exp(s - m), khot = 0, local sum
    float e[EPT], kh[EPT];
    float lsum = 0.0f;
#pragma unroll
    for (int i = 0; i < EPT; i++) {
        e[i]  = __expf(sv[i] - m);
        kh[i] = 0.0f;
        lsum += e[i];
    }

    // First block sum
    lsum = warpRedSum(lsum);
    if (lane == 0) red[wid] = lsum;
    __syncthreads();
    if (wid == 0) {
        float t = red[lane];
        t = warpRedSum(t);
        if (lane == 0) bcast = t;
    }
    __syncthreads();
    float Z = bcast;

    // K iterations. Last iteration skips the (unused) next-Z reduction.
#pragma unroll
    for (int k = 0; k < KITER; k++) {
        const float inv = 1.0f / Z;
        float ns = 0.0f;
#pragma unroll
        for (int i = 0; i < EPT; i++) {
            float p = e[i] * inv;
            kh[i] += p;
            float t = fmaxf(1.0f - p, EPSF);
            e[i] *= t;
            ns += e[i];
        }
        if (k < KITER - 1) {
            ns = warpRedSum(ns);
            if (lane == 0) red[wid] = ns;
            __syncthreads();
            if (wid == 0) {
                float t = red[lane];
                t = warpRedSum(t);
                if (lane == 0) bcast = t;
            }
            __syncthreads();
            Z = bcast;
        }
    }

    // Store khot, coalesced float4
#pragma unroll
    for (int c = 0; c < EPT / 4; c++) {
        float4 v;
        v.x = kh[c * 4 + 0];
        v.y = kh[c * 4 + 1];
        v.z = kh[c * 4 + 2];
        v.w = kh[c * 4 + 3];
        o4[tid + c * THREADS] = v;
    }
}

extern "C" void kernel_launch(void* const* d_in, const int* in_sizes, int n_in,
                              void* d_out, int out_size) {
    const float* scores = (const float*)d_in[0];
    const float* g      = (const float*)d_in[1];
    float* out          = (float*)d_out;
    subset_op_kernel<<<ROWS, THREADS>>>(scores, g, out);
}

// round 2
// speedup vs baseline: 2.7686x; 2.7686x over previous
#include <cuda_runtime.h>
#include <math_constants.h>

// SubsetOperator: soft k-hot relaxation (K=16, TAU=1).
//   s = scores + g;  repeat K: s += log(max(1-onehot,EPS)); onehot=softmax(s); khot+=onehot
// Exp-domain equivalent with e = exp(s - rowmax):
//   repeat K: Z = sum(e); p = e/Z; khot += p; e *= (1-p)
// Packed f32x2 form (tracking nk = -khot so only mul/add/fma are needed):
//   q = e * (-1/Z); nk += q; e = fma(q, e, e); ns += e

#define ROWS 4096
#define NCOL 8192
#define THREADS 512
#define EPT 16
#define PAIRS 8            // EPT/2 packed f32x2 values per thread
#define KITER 16

typedef unsigned long long u64;

#define MUL2(d, a, b)    asm("mul.rn.f32x2 %0, %1, %2;"     : "=l"(d) : "l"(a), "l"(b))
#define ADD2(d, a, b)    asm("add.rn.f32x2 %0, %1, %2;"     : "=l"(d) : "l"(a), "l"(b))
#define FMA2(d, a, b, c) asm("fma.rn.f32x2 %0, %1, %2, %3;" : "=l"(d) : "l"(a), "l"(b), "l"(c))
#define PACK2(d, lo, hi) asm("mov.b64 %0, {%1, %2};" : "=l"(d) : "f"(lo), "f"(hi))
#define UNPACK2(lo, hi, s) asm("mov.b64 {%0, %1}, %2;" : "=f"(lo), "=f"(hi) : "l"(s))

__device__ __forceinline__ float warpRedSum(float v) {
#pragma unroll
    for (int o = 16; o > 0; o >>= 1) v += __shfl_xor_sync(0xffffffffu, v, o);
    return v;
}
__device__ __forceinline__ float warpRedMax(float v) {
#pragma unroll
    for (int o = 16; o > 0; o >>= 1) v = fmaxf(v, __shfl_xor_sync(0xffffffffu, v, o));
    return v;
}

__global__ void __launch_bounds__(THREADS, 2)
subset_op_kernel(const float* __restrict__ scores,
                 const float* __restrict__ g,
                 float* __restrict__ out) {
    // Double-buffered partials: one __syncthreads per reduction.
    __shared__ float red0[16];
    __shared__ float red1[16];

    const int row  = blockIdx.x;
    const int tid  = threadIdx.x;
    const int lane = tid & 31;
    const int wid  = tid >> 5;

    const float4* __restrict__ s4 = (const float4*)(scores + (size_t)row * NCOL);
    const float4* __restrict__ g4 = (const float4*)(g      + (size_t)row * NCOL);
    float4* __restrict__ o4       = (float4*)(out          + (size_t)row * NCOL);

    float sv[EPT];
    float m = -CUDART_INF_F;

#pragma unroll
    for (int c = 0; c < EPT / 4; c++) {
        float4 a = s4[tid + c * THREADS];
        float4 b = g4[tid + c * THREADS];
        sv[c * 4 + 0] = a.x + b.x;
        sv[c * 4 + 1] = a.y + b.y;
        sv[c * 4 + 2] = a.z + b.z;
        sv[c * 4 + 3] = a.w + b.w;
#pragma unroll
        for (int j = 0; j < 4; j++) m = fmaxf(m, sv[c * 4 + j]);
    }

    // ---- block max (single barrier, redundant phase-2 in every warp) ----
    m = warpRedMax(m);
    if (lane == 0) red0[wid] = m;
    __syncthreads();
    {
        float t = (lane < 16) ? red0[lane] : -CUDART_INF_F;
        m = warpRedMax(t);
    }

    // ---- e = exp(s - m) packed; nk = 0; local sum ----
    u64 e[PAIRS], nk[PAIRS];
    float lsum = 0.0f;
#pragma unroll
    for (int j = 0; j < PAIRS; j++) {
        float e0 = __expf(sv[2 * j]     - m);
        float e1 = __expf(sv[2 * j + 1] - m);
        PACK2(e[j], e0, e1);
        nk[j] = 0ull;
        lsum += e0 + e1;
    }

    // ---- first Z (single barrier) ----
    lsum = warpRedSum(lsum);
    if (lane == 0) red1[wid] = lsum;
    __syncthreads();
    float Z;
    {
        float t = (lane < 16) ? red1[lane] : 0.0f;
        Z = warpRedSum(t);
    }

    // ---- K iterations ----
#pragma unroll
    for (int k = 0; k < KITER; k++) {
        const float ninv = -1.0f / Z;
        u64 ninv2;
        PACK2(ninv2, ninv, ninv);

        u64 nsa = 0ull, nsb = 0ull;
#pragma unroll
        for (int j = 0; j < PAIRS; j++) {
            u64 q;
            MUL2(q, e[j], ninv2);        // q = -p
            ADD2(nk[j], nk[j], q);       // nk -= p  (nk = -khot)
            FMA2(e[j], q, e[j], e[j]);   // e = e*(1-p)
            if (j & 1) { ADD2(nsb, nsb, e[j]); }
            else       { ADD2(nsa, nsa, e[j]); }
        }

        if (k < KITER - 1) {
            u64 ns2;
            ADD2(ns2, nsa, nsb);
            float lo, hi;
            UNPACK2(lo, hi, ns2);
            float ns = lo + hi;
            ns = warpRedSum(ns);
            if (k & 1) {
                if (lane == 0) red1[wid] = ns;
                __syncthreads();
                float t = (lane < 16) ? red1[lane] : 0.0f;
                Z = warpRedSum(t);
            } else {
                if (lane == 0) red0[wid] = ns;
                __syncthreads();
                float t = (lane < 16) ? red0[lane] : 0.0f;
                Z = warpRedSum(t);
            }
        }
    }

    // ---- store khot = -nk, coalesced float4 ----
#pragma unroll
    for (int c = 0; c < EPT / 4; c++) {
        float a0, a1, a2, a3;
        UNPACK2(a0, a1, nk[2 * c]);
        UNPACK2(a2, a3, nk[2 * c + 1]);
        float4 v;
        v.x = -a0; v.y = -a1; v.z = -a2; v.w = -a3;
        o4[tid + c * THREADS] = v;
    }
}

extern "C" void kernel_launch(void* const* d_in, const int* in_sizes, int n_in,
                              void* d_out, int out_size) {
    const float* scores = (const float*)d_in[0];
    const float* g      = (const float*)d_in[1];
    float* out          = (float*)d_out;
    subset_op_kernel<<<ROWS, THREADS>>>(scores, g, out);
}

// round 4
// speedup vs baseline: 2.8428x; 1.0268x over previous
#include <cuda_runtime.h>
#include <math_constants.h>
#include <cstdint>

// SubsetOperator soft k-hot (K=16, TAU=1), exp-domain:
//   e = exp(s0 - max); repeat K: p = e/Z; khot += p; e *= (1-p); Z' = Z - S2/Z (S2 = sum e^2)
// S2 depends only on e (not Z) -> reduction pipelined around one barrier/iter.

#define ROWS 4096
#define NCOL 8192
#define THREADS 512
#define PAIRS 8
#define KITER 16
#define GRID 296   // 2 CTAs per SM, persistent

typedef unsigned long long u64;
typedef unsigned int u32;

#define MUL2(d,a,b)    asm("mul.rn.f32x2 %0, %1, %2;"     : "=l"(d) : "l"(a), "l"(b))
#define ADD2(d,a,b)    asm("add.rn.f32x2 %0, %1, %2;"     : "=l"(d) : "l"(a), "l"(b))
#define FMA2(d,a,b,c)  asm("fma.rn.f32x2 %0, %1, %2, %3;" : "=l"(d) : "l"(a), "l"(b), "l"(c))
#define PACK2(d,lo,hi)   asm("mov.b64 %0, {%1, %2};" : "=l"(d) : "f"(lo), "f"(hi))
#define UNPACK2(lo,hi,s) asm("mov.b64 {%0, %1}, %2;" : "=f"(lo), "=f"(hi) : "l"(s))

__device__ __forceinline__ float rcp_fast(float x) {
    float r; asm("rcp.approx.f32 %0, %1;" : "=f"(r) : "f"(x)); return r;
}
__device__ __forceinline__ float ex2_fast(float x) {
    float r; asm("ex2.approx.f32 %0, %1;" : "=f"(r) : "f"(x)); return r;
}

__device__ __forceinline__ float warpRedSum(float v) {
#pragma unroll
    for (int o = 16; o > 0; o >>= 1) v += __shfl_xor_sync(0xffffffffu, v, o);
    return v;
}

__device__ __forceinline__ void cp16(u32 dst, const void* src) {
    asm volatile("cp.async.cg.shared.global [%0], [%1], 16;" :: "r"(dst), "l"(src));
}

__device__ __forceinline__ void prefetch_row(const float* s, const float* gg,
                                             int row, float* tile, int tid, bool valid) {
    if (valid) {
        const float4* s4 = (const float4*)(s + (size_t)row * NCOL);
        const float4* g4 = (const float4*)(gg + (size_t)row * NCOL);
        u32 ds = (u32)__cvta_generic_to_shared(tile);
#pragma unroll
        for (int c = 0; c < 4; c++) {
            cp16(ds + (u32)(tid + c * THREADS) * 16u,             s4 + tid + c * THREADS);
            cp16(ds + (u32)NCOL * 4u + (u32)(tid + c * THREADS) * 16u, g4 + tid + c * THREADS);
        }
    }
    asm volatile("cp.async.commit_group;");
}

__global__ void __launch_bounds__(THREADS, 2)
subset_op_kernel(const float* __restrict__ scores,
                 const float* __restrict__ g,
                 float* __restrict__ out) {
    extern __shared__ __align__(16) float tile[];   // 2 * NCOL floats = 64KB
    __shared__ __align__(16) float red[2][16];
    __shared__ __align__(16) float mred[16];

    const int tid  = threadIdx.x;
    const int lane = tid & 31;
    const int wid  = tid >> 5;

    int row = blockIdx.x;
    prefetch_row(scores, g, row, tile, tid, true);

    for (; row < ROWS; row += GRID) {
        asm volatile("cp.async.wait_group 0;");
        __syncthreads();

        // ---- pass 1: sv = scores + g (packed), row max ----
        u64 sv[PAIRS];
        float m = -CUDART_INF_F;
        const float4* ts4 = (const float4*)tile;
        const float4* tg4 = (const float4*)(tile + NCOL);
#pragma unroll
        for (int c = 0; c < 4; c++) {
            float4 a = ts4[tid + c * THREADS];
            float4 b = tg4[tid + c * THREADS];
            u64 a0, a1, b0, b1;
            PACK2(a0, a.x, a.y); PACK2(a1, a.z, a.w);
            PACK2(b0, b.x, b.y); PACK2(b1, b.z, b.w);
            ADD2(sv[2 * c], a0, b0);
            ADD2(sv[2 * c + 1], a1, b1);
            float x0, x1, x2, x3;
            UNPACK2(x0, x1, sv[2 * c]);
            UNPACK2(x2, x3, sv[2 * c + 1]);
            m = fmaxf(m, fmaxf(fmaxf(x0, x1), fmaxf(x2, x3)));
        }
#pragma unroll
        for (int o = 16; o > 0; o >>= 1) m = fmaxf(m, __shfl_xor_sync(0xffffffffu, m, o));
        if (lane == 0) mred[wid] = m;
        __syncthreads();
        {
            float4 v = *(const float4*)&mred[(lane & 3) * 4];
            m = fmaxf(fmaxf(v.x, v.y), fmaxf(v.z, v.w));
            m = fmaxf(m, __shfl_xor_sync(0xffffffffu, m, 1));
            m = fmaxf(m, __shfl_xor_sync(0xffffffffu, m, 2));
        }

        // ---- exp + local Z0 ----
        u64 e[PAIRS], kh[PAIRS];
        const float L2E = 1.4426950408889634f;
        const float cexp = -m * L2E;
        float zl = 0.0f;
#pragma unroll
        for (int j = 0; j < PAIRS; j++) {
            float x0, x1; UNPACK2(x0, x1, sv[j]);
            float e0 = ex2_fast(fmaf(x0, L2E, cexp));
            float e1 = ex2_fast(fmaf(x1, L2E, cexp));
            PACK2(e[j], e0, e1);
            kh[j] = 0ull;
            zl += e0 + e1;
        }
        zl = warpRedSum(zl);
        if (lane == 0) red[1][wid] = zl;
        __syncthreads();
        float Z;
        {
            float4 v = *(const float4*)&red[1][(lane & 3) * 4];
            float t = (v.x + v.y) + (v.z + v.w);
            t += __shfl_xor_sync(0xffffffffu, t, 1);
            t += __shfl_xor_sync(0xffffffffu, t, 2);
            Z = t;
        }
        float pinv = rcp_fast(Z);
        float ninv = -pinv;
        u64 pinv2, ninv2, one2;
        PACK2(pinv2, pinv, pinv);
        PACK2(ninv2, ninv, ninv);
        PACK2(one2, 1.0f, 1.0f);

        // tile is dead now -> prefetch next row under the iteration phase
        prefetch_row(scores, g, row + GRID, tile, tid, (row + GRID) < ROWS);

        // ---- iterations 0..14 (one barrier each, S2 pipelined) ----
#pragma unroll
        for (int k = 0; k < KITER - 1; k++) {
            const int buf = k & 1;
            // S2 partial = sum e^2 (independent of Z)
            u64 s2a, s2b;
            MUL2(s2a, e[0], e[0]);
            MUL2(s2b, e[1], e[1]);
            FMA2(s2a, e[2], e[2], s2a);
            FMA2(s2b, e[3], e[3], s2b);
            FMA2(s2a, e[4], e[4], s2a);
            FMA2(s2b, e[5], e[5], s2b);
            FMA2(s2a, e[6], e[6], s2a);
            FMA2(s2b, e[7], e[7], s2b);
            ADD2(s2a, s2a, s2b);
            float slo, shi; UNPACK2(slo, shi, s2a);
            float s = slo + shi;
            s = warpRedSum(s);
            if (lane == 0) red[buf][wid] = s;

            // khot += e * (1/Z)   (old e; hides the shuffle chain above)
#pragma unroll
            for (int j = 0; j < PAIRS; j++) FMA2(kh[j], e[j], pinv2, kh[j]);
            // e *= (1 - e/Z), first half before the barrier
#pragma unroll
            for (int j = 0; j < 4; j++) {
                u64 u; FMA2(u, e[j], ninv2, one2); MUL2(e[j], e[j], u);
            }
            __syncthreads();
            // second half after the barrier (hides the LDS/reduce tail)
#pragma unroll
            for (int j = 4; j < 8; j++) {
                u64 u; FMA2(u, e[j], ninv2, one2); MUL2(e[j], e[j], u);
            }
            // tail: total S2, Z' = Z - S2/Z, new inverses
            {
                float4 v = *(const float4*)&red[buf][(lane & 3) * 4];
                float t = (v.x + v.y) + (v.z + v.w);
                t += __shfl_xor_sync(0xffffffffu, t, 1);
                t += __shfl_xor_sync(0xffffffffu, t, 2);
                Z = fmaf(t, ninv, Z);
            }
            pinv = rcp_fast(Z);
            ninv = -pinv;
            PACK2(pinv2, pinv, pinv);
            PACK2(ninv2, ninv, ninv);
        }
        // ---- iteration 15: only khot accumulate ----
#pragma unroll
        for (int j = 0; j < PAIRS; j++) FMA2(kh[j], e[j], pinv2, kh[j]);

        // ---- store ----
        float4* o4 = (float4*)(out + (size_t)row * NCOL);
#pragma unroll
        for (int c = 0; c < 4; c++) {
            float a0, a1, a2, a3;
            UNPACK2(a0, a1, kh[2 * c]);
            UNPACK2(a2, a3, kh[2 * c + 1]);
            float4 v; v.x = a0; v.y = a1; v.z = a2; v.w = a3;
            o4[tid + c * THREADS] = v;
        }
    }
}

extern "C" void kernel_launch(void* const* d_in, const int* in_sizes, int n_in,
                              void* d_out, int out_size) {
    const float* scores = (const float*)d_in[0];
    const float* g      = (const float*)d_in[1];
    float* out          = (float*)d_out;
    cudaFuncSetAttribute(subset_op_kernel,
                         cudaFuncAttributeMaxDynamicSharedMemorySize, 2 * NCOL * 4);
    subset_op_kernel<<<GRID, THREADS, 2 * NCOL * 4>>>(scores, g, out);
}